// round 12
// baseline (speedup 1.0000x reference)
#include <cuda_runtime.h>
#include <cuda_fp16.h>
#include <cstdint>

// ===================== problem constants =====================
// x: 262144 rows x 128; W: (8,128,128); b: (8,128)
// CTA job: 128 rows x 128 cols x K=128. Warp = 16 exclusive M-rows, full N.
#define N_DIM      128
#define K_DIM      128
#define THREADS    256
#define NUM_CTAS   2048
#define K_CHUNK    32
#define NCHUNK     4

// ---- smem layout (32-bit words) ----
// [W image 8192][per-warp A bufs: 8 warps x 2 bufs x 640 words][bias 128]
#define OFF_W        0
#define W_IMG_WORDS  8192
#define AROW_W       20                        // words per A row (40 halves) -> LDSM conflict-free
#define ABUF_W       (16 * AROW_W)             // 320 words per buffer
#define WARP_A_W     (2 * ABUF_W)              // 640 words per warp (ping-pong)
#define OFF_A        W_IMG_WORDS               // 8192
#define OFF_BIAS     (OFF_A + 8 * WARP_A_W)    // 13312
#define SMEM_FLOATS  (OFF_BIAS + 128)
#define SMEM_BYTES   (SMEM_FLOATS * 4)         // 53,760 (x2 CTAs = 107.5KB)

// ===================== helpers =====================
__device__ __forceinline__ uint32_t smem_u32(const void* p) {
    uint32_t a;
    asm("{ .reg .u64 t; cvta.to.shared.u64 t, %1; cvt.u32.u64 %0, t; }" : "=r"(a) : "l"(p));
    return a;
}
__device__ __forceinline__ void cp_async16(uint32_t dst, const void* src) {
    asm volatile("cp.async.cg.shared.global [%0], [%1], 16;" :: "r"(dst), "l"(src));
}
#define CP_COMMIT()  asm volatile("cp.async.commit_group;" ::: "memory")
#define CP_WAIT(n)   asm volatile("cp.async.wait_group %0;" :: "n"(n) : "memory")

__device__ __forceinline__ void ldsm_x4(uint32_t& r0, uint32_t& r1, uint32_t& r2, uint32_t& r3,
                                        uint32_t addr) {
    asm volatile("ldmatrix.sync.aligned.m8n8.x4.shared.b16 {%0,%1,%2,%3}, [%4];"
                 : "=r"(r0), "=r"(r1), "=r"(r2), "=r"(r3) : "r"(addr));
}

// m16n8k16 fp16 MMA, fp32 accumulate
__device__ __forceinline__ void mma_f16(float* c, const uint32_t* a, uint32_t b0, uint32_t b1) {
    asm volatile(
        "mma.sync.aligned.m16n8k16.row.col.f32.f16.f16.f32 "
        "{%0,%1,%2,%3}, {%4,%5,%6,%7}, {%8,%9}, {%0,%1,%2,%3};"
        : "+f"(c[0]), "+f"(c[1]), "+f"(c[2]), "+f"(c[3])
        : "r"(a[0]), "r"(a[1]), "r"(a[2]), "r"(a[3]), "r"(b0), "r"(b1));
}

// ===================== W fp16 fragment image (validated rounds 8-11) =====================
// Per (ch, kc): 4096 halves (512 float4s). fi4 = (p*2+ks)*32+lane holds
// { b0(nt=2p), b1(nt=2p), b0(nt=2p+1), b1(nt=2p+1) } fp16x2 fragments,
// p = 16-col group (0..7), ks = k16 step (0..1) within the 32-k chunk.
__device__ __align__(16) __half g_Wimg[8 * 4 * 4096];

__global__ void prep_w_kernel(const float* __restrict__ W) {
    int idx = blockIdx.x * blockDim.x + threadIdx.x;   // 0 .. 131071
    if (idx >= 8 * 128 * 128) return;
    int ch = idx >> 14;
    int n  = (idx >> 7) & 127;
    int k  = idx & 127;
    int kc = k >> 5;
    int ks = (k >> 4) & 1;
    int bix = (k >> 3) & 1;
    int hsel = k & 1;
    int lane = ((n & 7) << 2) | ((k >> 1) & 3);
    int p = n >> 4;
    int ntodd = (n >> 3) & 1;
    int e = ntodd * 2 + bix;
    int fi4 = (p * 2 + ks) * 32 + lane;
    g_Wimg[(ch * 4 + kc) * 4096 + fi4 * 8 + e * 2 + hsel] = __float2half_rn(W[idx]);
}

// ===================== main GEMM (barrier-free mainloop) =====================
__global__ __launch_bounds__(THREADS, 2)
void gemm_kernel(const float* __restrict__ x, const float* __restrict__ bias,
                 float* __restrict__ out) {
    extern __shared__ __align__(16) float smem[];
    const uint32_t sm_base = smem_u32(smem);

    const int tid  = threadIdx.x;
    const int lane = tid & 31;
    const int wid  = tid >> 5;
    const int blk  = blockIdx.x;
    const int ch   = (blk >> 1) & 7;

    const float* a_base = x + (size_t)blk * (128 * K_DIM);
    float*       o_base = out + (size_t)blk * (128 * N_DIM);

    const int warpM = wid * 16;              // 16 exclusive rows per warp

    // ---- prologue: W image via cp.async; bias; warp's A chunk 0 via LDG ----
    {
        const __half* wsrc = g_Wimg + ch * 16384;
        uint32_t sw = sm_base + OFF_W * 4u;
#pragma unroll
        for (int j = 0; j < 8; j++) {
            int pid = j * THREADS + tid;
            cp_async16(sw + (uint32_t)pid * 16u, wsrc + pid * 8);
        }
        CP_COMMIT();
    }
    if (tid < 128) smem[OFF_BIAS + tid] = bias[ch * 128 + tid];

    // per-lane A load coords: i=0..3 -> local row li = i*4 + (lane>>3), col4 = lane&7
    const int lrow = lane >> 3;              // 0..3
    const int apc  = lane & 7;

    float4 v[4];
#pragma unroll
    for (int i = 0; i < 4; i++)
        v[i] = *(const float4*)(a_base + (size_t)(warpM + i * 4 + lrow) * K_DIM + apc * 4);

    CP_WAIT(0);
    __syncthreads();                         // the ONLY CTA barrier (W image + bias)

    // warp-private A buffers
    uint32_t* const mybuf = (uint32_t*)(smem + OFF_A + wid * WARP_A_W);

    // STS chunk 0 -> buf 0 (writer == reader warp; syncwarp suffices)
#pragma unroll
    for (int i = 0; i < 4; i++) {
        __half2 h0 = __float22half2_rn(make_float2(v[i].x, v[i].y));
        __half2 h1 = __float22half2_rn(make_float2(v[i].z, v[i].w));
        uint2 pk; pk.x = *(uint32_t*)&h0; pk.y = *(uint32_t*)&h1;
        *(uint2*)(mybuf + (i * 4 + lrow) * AROW_W + apc * 2) = pk;
    }
    __syncwarp();

    float acc[16][4];
#pragma unroll
    for (int nt = 0; nt < 16; nt++)
#pragma unroll
        for (int q = 0; q < 4; q++) acc[nt][q] = 0.0f;

    // LDSM per-lane byte address within warp buffer:
    // local row = (lane&7) + ((lane>>3)&1)*8 ; +8 halves for lanes 16-31
    const uint32_t aL0 = sm_base + (uint32_t)(OFF_A + wid * WARP_A_W) * 4u +
        (uint32_t)((((lane & 7) + ((lane >> 3) & 1) * 8) * AROW_W + (lane >> 4) * 4) * 4);

#pragma unroll
    for (int kc = 0; kc < NCHUNK; kc++) {
        const int par = kc & 1;

        // LDG next chunk (this warp's rows) — covered by MMA block below
        if (kc < NCHUNK - 1) {
#pragma unroll
            for (int i = 0; i < 4; i++)
                v[i] = *(const float4*)(a_base + (size_t)(warpM + i * 4 + lrow) * K_DIM
                                        + (kc + 1) * K_CHUNK + apc * 4);
        }

        // A fragments for both k16-steps of this chunk
        const uint32_t aL = aL0 + (uint32_t)(par * ABUF_W) * 4u;
        uint32_t afr[2][4];
        ldsm_x4(afr[0][0], afr[0][1], afr[0][2], afr[0][3], aL);
        ldsm_x4(afr[1][0], afr[1][1], afr[1][2], afr[1][3], aL + 32u);  // +16 halves

        // ---- MMA: full N=128 per warp, 2 ks x 8 p-groups (B in 2 reg-groups of 4) ----
        const float4* bW = (const float4*)(smem + OFF_W) + kc * 512 + lane;
#pragma unroll
        for (int ks = 0; ks < 2; ks++) {
#pragma unroll
            for (int pg = 0; pg < 2; pg++) {
                float4 f[4];
#pragma unroll
                for (int q = 0; q < 4; q++)
                    f[q] = bW[((pg * 4 + q) * 2 + ks) * 32];
#pragma unroll
                for (int q = 0; q < 4; q++) {
                    int p = pg * 4 + q;
                    uint32_t b0e = __float_as_uint(f[q].x), b1e = __float_as_uint(f[q].y);
                    uint32_t b0o = __float_as_uint(f[q].z), b1o = __float_as_uint(f[q].w);
                    mma_f16(acc[2 * p],     afr[ks], b0e, b1e);
                    mma_f16(acc[2 * p + 1], afr[ks], b0o, b1o);
                }
            }
        }

        // ---- cvt + STS next chunk into opposite warp-private buffer ----
        if (kc < NCHUNK - 1) {
            const int npar = par ^ 1;
#pragma unroll
            for (int i = 0; i < 4; i++) {
                __half2 h0 = __float22half2_rn(make_float2(v[i].x, v[i].y));
                __half2 h1 = __float22half2_rn(make_float2(v[i].z, v[i].w));
                uint2 pk; pk.x = *(uint32_t*)&h0; pk.y = *(uint32_t*)&h1;
                *(uint2*)(mybuf + npar * ABUF_W + (i * 4 + lrow) * AROW_W + apc * 2) = pk;
            }
            __syncwarp();
        }
    }

    // ---- epilogue: accum + bias -> gmem (each warp writes its 16 full rows) ----
    const float* sB = smem + OFF_BIAS;
    const int r0 = warpM + (lane >> 2);
    const int n0 = (lane & 3) * 2;
#pragma unroll
    for (int hh = 0; hh < 2; hh++) {
        int row = r0 + hh * 8;
        float* orow = o_base + (size_t)row * N_DIM;
#pragma unroll
        for (int nt = 0; nt < 16; nt++) {
            int n = n0 + nt * 8;
            float2 vv;
            vv.x = acc[nt][hh * 2 + 0] + sB[n];
            vv.y = acc[nt][hh * 2 + 1] + sB[n + 1];
            *(float2*)(orow + n) = vv;
        }
    }
}

// ===================== launch =====================
extern "C" void kernel_launch(void* const* d_in, const int* in_sizes, int n_in,
                              void* d_out, int out_size) {
    const float* x = (const float*)d_in[0];
    const float* W = (const float*)d_in[1];
    const float* b = (const float*)d_in[2];
    float* out = (float*)d_out;

    cudaFuncSetAttribute(gemm_kernel, cudaFuncAttributeMaxDynamicSharedMemorySize, SMEM_BYTES);

    prep_w_kernel<<<512, 256>>>(W);
    gemm_kernel<<<NUM_CTAS, THREADS, SMEM_BYTES>>>(x, b, out);
}